// round 14
// baseline (speedup 1.0000x reference)
#include <cuda_runtime.h>
#include <cuda_fp16.h>
#include <cstdint>

#define NNODES 100000
#define NEDGES 600000
#define HIDDEN 128
#define HEADS  8
#define DH     16
#define NEG_SLOPE 0.2f
#define NSEG (2 * NNODES)            // (sign, node) segments

// ------------------------- scratch (static device globals) -------------------
__device__ __half g_feat16[2 * NNODES * HIDDEN]; // transformed features (fp16), per sign
__device__ float g_el  [2 * NNODES * HEADS];
__device__ float g_er  [2 * NNODES * HEADS];
__device__ int   g_cnt [NSEG];                  // per-seg in-degree (self-zeroing)
__device__ int   g_off [NSEG];                  // segment start offsets
__device__ int   g_cur [NSEG];                  // scatter cursors (end after scatter)
__device__ int   g_total;                       // block-base allocator (self-zeroing)
__device__ int   g_srcs[2 * NEDGES];            // src ids, bucketed by (sign,dst)

// ------------------------- histogram of dst ----------------------------------
__global__ void hist_kernel(const int* __restrict__ pd, const int* __restrict__ nd,
                            int e) {
    int i = blockIdx.x * blockDim.x + threadIdx.x;
    if (i >= 2 * e) return;
    int sign = (i >= e);
    int d = sign ? nd[i - e] : pd[i];
    atomicAdd(&g_cnt[sign * NNODES + d], 1);
}

// ------------------------- fused allocator scan ------------------------------
__global__ __launch_bounds__(256)
void scan_fused(int ntot) {
    __shared__ int wsum[8];
    __shared__ int sbase;
    int tid = threadIdx.x;
    int lane = tid & 31, wid = tid >> 5;
    int base = blockIdx.x * 1024 + tid * 4;
    int v[4];
#pragma unroll
    for (int j = 0; j < 4; j++)
        v[j] = (base + j < ntot) ? g_cnt[base + j] : 0;
#pragma unroll
    for (int j = 0; j < 4; j++)
        if (base + j < ntot) g_cnt[base + j] = 0;
    int local = v[0] + v[1] + v[2] + v[3];
    int x = local;
#pragma unroll
    for (int o = 1; o < 32; o <<= 1) {
        int t = __shfl_up_sync(0xffffffffu, x, o);
        if (lane >= o) x += t;
    }
    if (lane == 31) wsum[wid] = x;
    __syncthreads();
    if (tid == 0) {
        int run = 0;
#pragma unroll
        for (int w = 0; w < 8; w++) { int t = wsum[w]; wsum[w] = run; run += t; }
        sbase = atomicAdd(&g_total, run);
    }
    __syncthreads();
    int run = sbase + wsum[wid] + (x - local);
#pragma unroll
    for (int j = 0; j < 4; j++) {
        if (base + j < ntot) { g_off[base + j] = run; g_cur[base + j] = run; }
        run += v[j];
    }
}

// ------------------------- scatter src ids into buckets ----------------------
__global__ void scatter_kernel(const int* __restrict__ ps, const int* __restrict__ pd,
                               const int* __restrict__ ns, const int* __restrict__ nd,
                               int e) {
    int i = blockIdx.x * blockDim.x + threadIdx.x;
    if (i == 0) g_total = 0;
    if (i >= 2 * e) return;
    int sign = (i >= e);
    int j = sign ? i - e : i;
    int s = sign ? ns[j] : ps[j];
    int d = sign ? nd[j] : pd[j];
    int pos = atomicAdd(&g_cur[sign * NNODES + d], 1);
    g_srcs[pos] = s;
}

// ------------------------- fp16 helpers --------------------------------------
__device__ __forceinline__ uint32_t f2h2(float lo, float hi) {
    __half2 h = __floats2half2_rn(lo, hi);
    return *(uint32_t*)&h;
}

#define MMA_F16(cr, a, b)                                                      \
    asm volatile("mma.sync.aligned.m16n8k16.row.col.f32.f16.f16.f32 "          \
                 "{%0,%1,%2,%3},{%4,%5,%6,%7},{%8,%9},{%0,%1,%2,%3};"          \
                 : "+f"((cr)[0]), "+f"((cr)[1]), "+f"((cr)[2]), "+f"((cr)[3])  \
                 : "r"((a)[0]), "r"((a)[1]), "r"((a)[2]), "r"((a)[3]),         \
                   "r"((b)[0]), "r"((b)[1]))

// ------------------------- tensor-core fp16 GEMM (feature pass) --------------
__global__ __launch_bounds__(256, 2)
void gemm_feat(const float* __restrict__ A0, int M, int K,
               const float* __restrict__ B0, const float* __restrict__ B1,
               __half* __restrict__ C0, __half* __restrict__ C1,
               const float* __restrict__ al0, const float* __restrict__ ar0,
               float* __restrict__ el0, float* __restrict__ er0,
               const float* __restrict__ al1, const float* __restrict__ ar1,
               float* __restrict__ el1, float* __restrict__ er1) {
    constexpr int NT = 128;
    constexpr int ASTR = 12;
    constexpr int BSTR = NT + 8;
    constexpr int WN   = NT / 2;
    constexpr int NJ   = WN / 8;
    constexpr int ASZ  = 128 * ASTR;
    constexpr int BSZ  = 8 * BSTR;

    __shared__ __align__(16) uint32_t As[2 * ASZ];
    __shared__ __align__(16) uint32_t Bs[2 * BSZ];

    const float* B  = B0;
    __half*      C  = C0;
    const float* al = al0; const float* ar = ar0;
    float*       el = el0; float*       er = er0;
    if (blockIdx.y == 1) { B = B1; C = C1; al = al1; ar = ar1; el = el1; er = er1; }

    const int tid  = threadIdx.x;
    const int wid  = tid >> 5;
    const int lane = tid & 31;
    const int g    = lane >> 2;
    const int tig  = lane & 3;
    const int wm   = wid & 3;
    const int wn   = wid >> 2;
    const int m0   = blockIdx.x * 128;

    float c[2][NJ][4];
#pragma unroll
    for (int mi = 0; mi < 2; mi++)
#pragma unroll
        for (int nj = 0; nj < NJ; nj++)
#pragma unroll
            for (int q = 0; q < 4; q++) c[mi][nj][q] = 0.0f;

    float4 pa[2], pb[2];

#define LOAD_A(k0, i, dstv) do {                                               \
        int idx = tid + (i) * 256;                                             \
        int row = idx >> 2; int kk = (idx & 3) * 4;                            \
        int grow = m0 + row;                                                   \
        if (grow < M) {                                                        \
            dstv = *(const float4*)(A0 + (size_t)grow * 128 + (k0) + kk);      \
        } else dstv = make_float4(0.f, 0.f, 0.f, 0.f);                         \
    } while (0)
#define LOAD_B(k0) do {                                                        \
        int kp = tid >> 5, n4 = (tid & 31) * 4;                                \
        pb[0] = *(const float4*)(B + (size_t)((k0) + 2 * kp)     * NT + n4);   \
        pb[1] = *(const float4*)(B + (size_t)((k0) + 2 * kp + 1) * NT + n4);   \
    } while (0)
#define COMMIT(p) do {                                                         \
        _Pragma("unroll")                                                      \
        for (int i = 0; i < 2; i++) {                                          \
            int idx = tid + i * 256;                                           \
            int row = idx >> 2; int kp0 = (idx & 3) * 2;                       \
            uint2 t = make_uint2(f2h2(pa[i].x, pa[i].y), f2h2(pa[i].z, pa[i].w)); \
            *(uint2*)&As[(p) * ASZ + row * ASTR + kp0] = t;                    \
        }                                                                      \
        {                                                                      \
            int kp = tid >> 5, n4 = (tid & 31) * 4;                            \
            uint4 t = make_uint4(f2h2(pb[0].x, pb[1].x), f2h2(pb[0].y, pb[1].y), \
                                 f2h2(pb[0].z, pb[1].z), f2h2(pb[0].w, pb[1].w)); \
            *(uint4*)&Bs[(p) * BSZ + kp * BSTR + n4] = t;                      \
        }                                                                      \
    } while (0)

    LOAD_A(0, 0, pa[0]); LOAD_A(0, 1, pa[1]);
    LOAD_B(0);
    COMMIT(0);
    __syncthreads();
    if (K > 16) {
        LOAD_A(16, 0, pa[0]); LOAD_A(16, 1, pa[1]);
        LOAD_B(16);
    }

    int p = 0;
    for (int k0 = 0; k0 < K; k0 += 16) {
        if (k0 + 16 < K) {
            COMMIT(p ^ 1);
            if (k0 + 32 < K) {
                LOAD_A(k0 + 32, 0, pa[0]); LOAD_A(k0 + 32, 1, pa[1]);
                LOAD_B(k0 + 32);
            }
        }
        const uint32_t* Ap = &As[p * ASZ];
        const uint32_t* Bp = &Bs[p * BSZ];
        uint32_t af[2][4];
#pragma unroll
        for (int mi = 0; mi < 2; mi++) {
            int mb = wm * 32 + mi * 16;
            af[mi][0] = Ap[(mb + g)     * ASTR + tig];
            af[mi][1] = Ap[(mb + 8 + g) * ASTR + tig];
            af[mi][2] = Ap[(mb + g)     * ASTR + tig + 4];
            af[mi][3] = Ap[(mb + 8 + g) * ASTR + tig + 4];
        }
        uint32_t bf[NJ][2];
#pragma unroll
        for (int nj = 0; nj < NJ; nj++) {
            int nb = wn * WN + nj * 8;
            bf[nj][0] = Bp[tig       * BSTR + nb + g];
            bf[nj][1] = Bp[(tig + 4) * BSTR + nb + g];
        }
#pragma unroll
        for (int mi = 0; mi < 2; mi++)
#pragma unroll
            for (int nj = 0; nj < NJ; nj++)
                MMA_F16(c[mi][nj], af[mi], bf[nj]);
        __syncthreads();
        p ^= 1;
    }
#undef LOAD_A
#undef LOAD_B
#undef COMMIT

    // ---- fused el/er epilogue ----
#pragma unroll
    for (int mi = 0; mi < 2; mi++) {
#pragma unroll
        for (int h = 0; h < 4; h++) {
            float e0 = 0.f, e1 = 0.f, r0v = 0.f, r1v = 0.f;
#pragma unroll
            for (int q = 0; q < 2; q++) {
                int nj = 2 * h + q;
                int col = wn * 64 + nj * 8 + 2 * tig;
                float a0 = al[col], a1 = al[col + 1];
                float b0 = ar[col], b1 = ar[col + 1];
                e0  += c[mi][nj][0] * a0 + c[mi][nj][1] * a1;
                e1  += c[mi][nj][2] * a0 + c[mi][nj][3] * a1;
                r0v += c[mi][nj][0] * b0 + c[mi][nj][1] * b1;
                r1v += c[mi][nj][2] * b0 + c[mi][nj][3] * b1;
            }
            e0  += __shfl_xor_sync(0xffffffffu, e0, 1);
            e0  += __shfl_xor_sync(0xffffffffu, e0, 2);
            e1  += __shfl_xor_sync(0xffffffffu, e1, 1);
            e1  += __shfl_xor_sync(0xffffffffu, e1, 2);
            r0v += __shfl_xor_sync(0xffffffffu, r0v, 1);
            r0v += __shfl_xor_sync(0xffffffffu, r0v, 2);
            r1v += __shfl_xor_sync(0xffffffffu, r1v, 1);
            r1v += __shfl_xor_sync(0xffffffffu, r1v, 2);
            if (tig == 0) {
                int hg = wn * 4 + h;
                int ra = m0 + wm * 32 + mi * 16 + g;
                int rb = ra + 8;
                if (ra < M) { el[ra * HEADS + hg] = e0;  er[ra * HEADS + hg] = r0v; }
                if (rb < M) { el[rb * HEADS + hg] = e1;  er[rb * HEADS + hg] = r1v; }
            }
        }
    }

    // ---- store C (fp16) ----
#pragma unroll
    for (int mi = 0; mi < 2; mi++) {
        int ra = m0 + wm * 32 + mi * 16 + g;
        int rb = ra + 8;
#pragma unroll
        for (int nj = 0; nj < NJ; nj++) {
            int col = wn * WN + nj * 8 + 2 * tig;
            if (ra < M) *(__half2*)&C[(size_t)ra * NT + col] =
                __floats2half2_rn(c[mi][nj][0], c[mi][nj][1]);
            if (rb < M) *(__half2*)&C[(size_t)rb * NT + col] =
                __floats2half2_rn(c[mi][nj][2], c[mi][nj][3]);
        }
    }
}

// ------------------------- fused aggregate + MLP kernel ----------------------
// Phase A: 16 half-warps x 16 (sign,node) segments each: CSR gather softmax
//   aggregation; h row written fp32 to out AND fp16 into stage-1 A smem.
// Phase B (stage 1): [128,256] @ W1[256,128] from smem A, W1 double-buffered.
// Phase C (stage 2): relu-hidden (Hs, aliases A_h[0..8192)) @ W2 (B2s, aliases
//   A_h[8192..12288) — A_h fully dead after stage-1's final sync) -> h_final.
#define AGG_ASTR 132                              // u32 per A row (128 kpairs + 4 pad)
#define AGG_ASZ  (128 * AGG_ASTR)                 // 16896 u32
#define AGG_BSTR 136
#define AGG_BSZ  (8 * AGG_BSTR)                   // 1088 u32
#define AGG_SMEM_BYTES ((AGG_ASZ + 2 * AGG_BSZ) * 4)   // 76288 B

__global__ __launch_bounds__(256, 2)
void agg_mlp_fused(float* __restrict__ out,
                   const float* __restrict__ b_pos, const float* __restrict__ b_neg,
                   int n,
                   const float* __restrict__ W1, const float* __restrict__ b1,
                   const float* __restrict__ W2, const float* __restrict__ b2,
                   float* __restrict__ outF) {
    extern __shared__ __align__(16) uint32_t smem[];
    uint32_t* A_h = smem;                 // [128][AGG_ASTR]
    uint32_t* Bs  = smem + AGG_ASZ;       // 2 stages of [8][AGG_BSTR]
    uint32_t* Hs  = smem;                 // stage2: [128][64]  (8192 u32, in A_h)
    uint32_t* B2s = smem + 8192;          // stage2: [64][64]   (4096 u32, in A_h)

    const int tid  = threadIdx.x;
    const int wid  = tid >> 5;
    const int lane = tid & 31;
    const int g    = lane >> 2;
    const int tig  = lane & 3;
    const int wm   = wid & 3;
    const int wn   = wid >> 2;
    const int m0   = blockIdx.x * 128;

    // ================= Phase A: aggregation =================
    {
        const int hw  = tid >> 4;         // 0..15
        const int l16 = tid & 15;
        const int h   = l16 >> 1;
        const float4 bp0 = *(const float4*)(b_pos + l16 * 8);
        const float4 bp1 = *(const float4*)(b_pos + l16 * 8 + 4);
        const float4 bn0 = *(const float4*)(b_neg + l16 * 8);
        const float4 bn1 = *(const float4*)(b_neg + l16 * 8 + 4);

        for (int i = 0; i < 16; i++) {
            int segidx = hw * 16 + i;     // 0..255
            int sign = segidx >> 7;
            int r = segidx & 127;
            int node = m0 + r;
            uint32_t* arow = &A_h[r * AGG_ASTR + sign * 64 + l16 * 4];
            if (node >= n) {
                *(uint4*)arow = make_uint4(0u, 0u, 0u, 0u);
                continue;
            }
            int seg = sign * NNODES + node;
            float er_h = g_er[(size_t)sign * NNODES * HEADS + (size_t)node * HEADS + h];
            const float* elb = g_el + (size_t)sign * NNODES * HEADS;
            const __half* fb = g_feat16 + (size_t)sign * NNODES * HIDDEN;
            int start = g_off[seg];
            int end   = g_cur[seg];

            float acc[8] = {};
            float den = 0.f;
#define ACC8(rr, ex) do {                                                      \
            float2 t;                                                          \
            t = __half22float2(*(__half2*)&(rr).x);                            \
            acc[0] = fmaf((ex), t.x, acc[0]); acc[1] = fmaf((ex), t.y, acc[1]);\
            t = __half22float2(*(__half2*)&(rr).y);                            \
            acc[2] = fmaf((ex), t.x, acc[2]); acc[3] = fmaf((ex), t.y, acc[3]);\
            t = __half22float2(*(__half2*)&(rr).z);                            \
            acc[4] = fmaf((ex), t.x, acc[4]); acc[5] = fmaf((ex), t.y, acc[5]);\
            t = __half22float2(*(__half2*)&(rr).w);                            \
            acc[6] = fmaf((ex), t.x, acc[6]); acc[7] = fmaf((ex), t.y, acc[7]);\
        } while (0)
            int k = start;
            for (; k + 1 < end; k += 2) {
                int s0 = g_srcs[k];
                int s1 = g_srcs[k + 1];
                float eh0 = elb[(size_t)s0 * HEADS + h] + er_h;
                float eh1 = elb[(size_t)s1 * HEADS + h] + er_h;
                uint4 r0 = *(const uint4*)&fb[(size_t)s0 * HIDDEN + l16 * 8];
                uint4 r1 = *(const uint4*)&fb[(size_t)s1 * HIDDEN + l16 * 8];
                eh0 = (eh0 > 0.f) ? eh0 : NEG_SLOPE * eh0;
                eh1 = (eh1 > 0.f) ? eh1 : NEG_SLOPE * eh1;
                float ex0 = __expf(eh0);
                float ex1 = __expf(eh1);
                den += ex0 + ex1;
                ACC8(r0, ex0);
                ACC8(r1, ex1);
            }
            if (k < end) {
                int s = g_srcs[k];
                float eh = elb[(size_t)s * HEADS + h] + er_h;
                eh = (eh > 0.f) ? eh : NEG_SLOPE * eh;
                float ex = __expf(eh);
                den += ex;
                uint4 rr = *(const uint4*)&fb[(size_t)s * HIDDEN + l16 * 8];
                ACC8(rr, ex);
            }
#undef ACC8
            float inv = (den > 0.f) ? (1.0f / den) : 0.0f;
            float4 b0 = sign ? bn0 : bp0;
            float4 b1v = sign ? bn1 : bp1;
            float o0 = acc[0] * inv + b0.x, o1 = acc[1] * inv + b0.y;
            float o2 = acc[2] * inv + b0.z, o3 = acc[3] * inv + b0.w;
            float o4 = acc[4] * inv + b1v.x, o5 = acc[5] * inv + b1v.y;
            float o6 = acc[6] * inv + b1v.z, o7 = acc[7] * inv + b1v.w;
            float* orow = &out[((size_t)sign * n + node) * HIDDEN + l16 * 8];
            *(float4*)orow       = make_float4(o0, o1, o2, o3);
            *(float4*)(orow + 4) = make_float4(o4, o5, o6, o7);
            *(uint4*)arow = make_uint4(f2h2(o0, o1), f2h2(o2, o3),
                                       f2h2(o4, o5), f2h2(o6, o7));
        }
    }

    // ================= Phase B: stage-1 GEMM [128,256] @ W1 =================
    float c[2][8][4];
#pragma unroll
    for (int mi = 0; mi < 2; mi++)
#pragma unroll
        for (int nj = 0; nj < 8; nj++)
#pragma unroll
            for (int q = 0; q < 4; q++) c[mi][nj][q] = 0.0f;

    float4 pb[2];
#define LOAD_B1(k0) do {                                                       \
        int kp = tid >> 5, n4 = (tid & 31) * 4;                                \
        pb[0] = *(const float4*)(W1 + (size_t)((k0) + 2 * kp)     * 128 + n4); \
        pb[1] = *(const float4*)(W1 + (size_t)((k0) + 2 * kp + 1) * 128 + n4); \
    } while (0)
#define COMMIT_B1(p) do {                                                      \
        int kp = tid >> 5, n4 = (tid & 31) * 4;                                \
        uint4 t = make_uint4(f2h2(pb[0].x, pb[1].x), f2h2(pb[0].y, pb[1].y),   \
                             f2h2(pb[0].z, pb[1].z), f2h2(pb[0].w, pb[1].w));  \
        *(uint4*)&Bs[(p) * AGG_BSZ + kp * AGG_BSTR + n4] = t;                  \
    } while (0)

    LOAD_B1(0);
    COMMIT_B1(0);
    __syncthreads();        // covers A_h writes + B stage 0
    LOAD_B1(16);

    int p = 0;
    for (int k0 = 0; k0 < 256; k0 += 16) {
        if (k0 + 16 < 256) {
            COMMIT_B1(p ^ 1);
            if (k0 + 32 < 256) LOAD_B1(k0 + 32);
        }
        const uint32_t* Bp = &Bs[p * AGG_BSZ];
        const int kb = k0 >> 1;     // kpair base
        uint32_t af[2][4];
#pragma unroll
        for (int mi = 0; mi < 2; mi++) {
            int mb = wm * 32 + mi * 16;
            af[mi][0] = A_h[(mb + g)     * AGG_ASTR + kb + tig];
            af[mi][1] = A_h[(mb + 8 + g) * AGG_ASTR + kb + tig];
            af[mi][2] = A_h[(mb + g)     * AGG_ASTR + kb + tig + 4];
            af[mi][3] = A_h[(mb + 8 + g) * AGG_ASTR + kb + tig + 4];
        }
        uint32_t bf[8][2];
#pragma unroll
        for (int nj = 0; nj < 8; nj++) {
            int nb = wn * 64 + nj * 8;
            bf[nj][0] = Bp[tig       * AGG_BSTR + nb + g];
            bf[nj][1] = Bp[(tig + 4) * AGG_BSTR + nb + g];
        }
#pragma unroll
        for (int mi = 0; mi < 2; mi++)
#pragma unroll
            for (int nj = 0; nj < 8; nj++)
                MMA_F16(c[mi][nj], af[mi], bf[nj]);
        __syncthreads();
        p ^= 1;
    }
#undef LOAD_B1
#undef COMMIT_B1
    // A_h fully dead here (final loop iteration ended with __syncthreads).

    // ---- write hidden (bias + relu, fp16) into Hs, swizzle kp ^ (g<<2) ----
#pragma unroll
    for (int mi = 0; mi < 2; mi++) {
        int ra = wm * 32 + mi * 16 + g;
        int rb = ra + 8;
#pragma unroll
        for (int nj = 0; nj < 8; nj++) {
            int col = wn * 64 + nj * 8 + 2 * tig;
            float bx = b1[col], by = b1[col + 1];
            float v0 = fmaxf(c[mi][nj][0] + bx, 0.f);
            float v1 = fmaxf(c[mi][nj][1] + by, 0.f);
            float v2 = fmaxf(c[mi][nj][2] + bx, 0.f);
            float v3 = fmaxf(c[mi][nj][3] + by, 0.f);
            int cp = wn * 32 + nj * 4 + tig;
            Hs[ra * 64 + (cp ^ (g << 2))] = f2h2(v0, v1);
            Hs[rb * 64 + (cp ^ (g << 2))] = f2h2(v2, v3);
        }
    }

    // ---- load W2 [128,64] into B2s, swizzle n ^ ((kp&3)<<3) ----
#pragma unroll
    for (int i = 0; i < 4; i++) {
        int idx = tid + i * 256;
        int kp = idx >> 4;
        int n4 = (idx & 15) * 4;
        float4 ev = *(const float4*)(W2 + (size_t)(2 * kp)     * 64 + n4);
        float4 ov = *(const float4*)(W2 + (size_t)(2 * kp + 1) * 64 + n4);
        uint4 t = make_uint4(f2h2(ev.x, ov.x), f2h2(ev.y, ov.y),
                             f2h2(ev.z, ov.z), f2h2(ev.w, ov.w));
        *(uint4*)&B2s[kp * 64 + (n4 ^ ((kp & 3) << 3))] = t;
    }
    __syncthreads();

    // ---- stage 2: [128,128] @ [128,64], 8 k16 steps ----
    float c2[2][4][4];
#pragma unroll
    for (int mi = 0; mi < 2; mi++)
#pragma unroll
        for (int nj = 0; nj < 4; nj++)
#pragma unroll
            for (int q = 0; q < 4; q++) c2[mi][nj][q] = 0.0f;

#pragma unroll
    for (int ks8 = 0; ks8 < 8; ks8++) {
        int kp0 = ks8 * 8;
        uint32_t af[2][4];
#pragma unroll
        for (int mi = 0; mi < 2; mi++) {
            int mb = wm * 32 + mi * 16;
            af[mi][0] = Hs[(mb + g)     * 64 + ((kp0 + tig)     ^ (g << 2))];
            af[mi][1] = Hs[(mb + 8 + g) * 64 + ((kp0 + tig)     ^ (g << 2))];
            af[mi][2] = Hs[(mb + g)     * 64 + ((kp0 + tig + 4) ^ (g << 2))];
            af[mi][3] = Hs[(mb + 8 + g) * 64 + ((kp0 + tig + 4) ^ (g << 2))];
        }
        uint32_t bf[4][2];
#pragma unroll
        for (int nj = 0; nj < 4; nj++) {
            int nb = wn * 32 + nj * 8 + g;
            bf[nj][0] = B2s[(kp0 + tig)     * 64 + (nb ^ (tig << 3))];
            bf[nj][1] = B2s[(kp0 + tig + 4) * 64 + (nb ^ (tig << 3))];
        }
#pragma unroll
        for (int mi = 0; mi < 2; mi++)
#pragma unroll
            for (int nj = 0; nj < 4; nj++)
                MMA_F16(c2[mi][nj], af[mi], bf[nj]);
    }

    // ---- store h_final (fp32, + b2) ----
#pragma unroll
    for (int mi = 0; mi < 2; mi++) {
        int ra = m0 + wm * 32 + mi * 16 + g;
        int rb = ra + 8;
#pragma unroll
        for (int nj = 0; nj < 4; nj++) {
            int col = wn * 32 + nj * 8 + 2 * tig;
            float bx = b2[col], by = b2[col + 1];
            if (ra < n) *(float2*)&outF[(size_t)ra * 64 + col] =
                make_float2(c2[mi][nj][0] + bx, c2[mi][nj][1] + by);
            if (rb < n) *(float2*)&outF[(size_t)rb * 64 + col] =
                make_float2(c2[mi][nj][2] + bx, c2[mi][nj][3] + by);
        }
    }
}

// ------------------------- launcher ------------------------------------------
extern "C" void kernel_launch(void* const* d_in, const int* in_sizes, int n_in,
                              void* d_out, int out_size) {
    const float* features = (const float*)d_in[0];
    const int*   pos_src  = (const int*)d_in[1];
    const int*   pos_dst  = (const int*)d_in[2];
    const int*   neg_src  = (const int*)d_in[3];
    const int*   neg_dst  = (const int*)d_in[4];
    const float* W_pos    = (const float*)d_in[5];
    const float* al_pos   = (const float*)d_in[6];
    const float* ar_pos   = (const float*)d_in[7];
    const float* b_pos    = (const float*)d_in[8];
    const float* W_neg    = (const float*)d_in[9];
    const float* al_neg   = (const float*)d_in[10];
    const float* ar_neg   = (const float*)d_in[11];
    const float* b_neg    = (const float*)d_in[12];
    const float* W1       = (const float*)d_in[13];
    const float* b1       = (const float*)d_in[14];
    const float* W2       = (const float*)d_in[15];
    const float* b2       = (const float*)d_in[16];
    float* out = (float*)d_out;

    int n = in_sizes[0] / HIDDEN;   // 100000
    int e = in_sizes[1];            // 600000

    void* p;
    cudaGetSymbolAddress(&p, g_feat16); __half* featp = (__half*)p;
    cudaGetSymbolAddress(&p, g_el);     float*  elp   = (float*)p;
    cudaGetSymbolAddress(&p, g_er);     float*  erp   = (float*)p;

    float* h_final = out + (size_t)2 * n * HIDDEN;

    int gb   = (n + 127) / 128;
    int nseg = 2 * n;
    int nb   = (nseg + 1023) / 1024;

    // one-time (idempotent, host-side) smem opt-in for the fused kernel
    cudaFuncSetAttribute(agg_mlp_fused,
                         cudaFuncAttributeMaxDynamicSharedMemorySize,
                         AGG_SMEM_BYTES);

    // Fork a side stream for the CSR build (independent of the feature GEMMs).
    cudaStream_t s1;
    cudaEvent_t ev_fork, ev_join;
    cudaStreamCreateWithFlags(&s1, cudaStreamNonBlocking);
    cudaEventCreateWithFlags(&ev_fork, cudaEventDisableTiming);
    cudaEventCreateWithFlags(&ev_join, cudaEventDisableTiming);

    cudaEventRecord(ev_fork, 0);
    cudaStreamWaitEvent(s1, ev_fork, 0);

    // --- side stream: CSR build ---
    hist_kernel<<<(2 * e + 255) / 256, 256, 0, s1>>>(pos_dst, neg_dst, e);
    scan_fused<<<nb, 256, 0, s1>>>(nseg);
    scatter_kernel<<<(2 * e + 255) / 256, 256, 0, s1>>>(pos_src, pos_dst, neg_src, neg_dst, e);
    cudaEventRecord(ev_join, s1);

    // --- main stream: feature transform GEMMs (fp16 MMA, both signs) ---
    {
        dim3 grid(gb, 2);
        gemm_feat<<<grid, 256>>>(
            features, n, HIDDEN,
            W_pos, W_neg,
            featp, featp + (size_t)NNODES * HIDDEN,
            al_pos, ar_pos, elp, erp,
            al_neg, ar_neg,
            elp + (size_t)NNODES * HEADS, erp + (size_t)NNODES * HEADS);
    }

    // join: fused kernel needs CSR + features
    cudaStreamWaitEvent(0, ev_join, 0);

    // --- fused aggregate + MLP ---
    agg_mlp_fused<<<gb, 256, AGG_SMEM_BYTES>>>(
        out, b_pos, b_neg, n, W1, b1, W2, b2, h_final);
}

// round 15
// speedup vs baseline: 1.3240x; 1.3240x over previous
#include <cuda_runtime.h>
#include <cuda_fp16.h>
#include <cstdint>

#define NNODES 100000
#define NEDGES 600000
#define HIDDEN 128
#define HEADS  8
#define DH     16
#define NEG_SLOPE 0.2f
#define NSEG (2 * NNODES)            // (sign, node) segments

// ------------------------- scratch (static device globals) -------------------
__device__ __half g_feat16[2 * NNODES * HIDDEN]; // transformed features (fp16), per sign
__device__ float g_el  [2 * NNODES * HEADS];
__device__ float g_er  [2 * NNODES * HEADS];
__device__ int   g_cnt [NSEG];                  // per-seg in-degree (self-zeroing)
__device__ int   g_off [NSEG];                  // segment start offsets
__device__ int   g_cur [NSEG];                  // scatter cursors (end after scatter)
__device__ int   g_total;                       // block-base allocator (self-zeroing)
__device__ int   g_srcs[2 * NEDGES];            // src ids, bucketed by (sign,dst)

// ------------------------- histogram of dst ----------------------------------
__global__ void hist_kernel(const int* __restrict__ pd, const int* __restrict__ nd,
                            int e) {
    int i = blockIdx.x * blockDim.x + threadIdx.x;
    if (i >= 2 * e) return;
    int sign = (i >= e);
    int d = sign ? nd[i - e] : pd[i];
    atomicAdd(&g_cnt[sign * NNODES + d], 1);
}

// ------------------------- fused allocator scan ------------------------------
__global__ __launch_bounds__(256)
void scan_fused(int ntot) {
    __shared__ int wsum[8];
    __shared__ int sbase;
    int tid = threadIdx.x;
    int lane = tid & 31, wid = tid >> 5;
    int base = blockIdx.x * 1024 + tid * 4;
    int v[4];
#pragma unroll
    for (int j = 0; j < 4; j++)
        v[j] = (base + j < ntot) ? g_cnt[base + j] : 0;
#pragma unroll
    for (int j = 0; j < 4; j++)
        if (base + j < ntot) g_cnt[base + j] = 0;
    int local = v[0] + v[1] + v[2] + v[3];
    int x = local;
#pragma unroll
    for (int o = 1; o < 32; o <<= 1) {
        int t = __shfl_up_sync(0xffffffffu, x, o);
        if (lane >= o) x += t;
    }
    if (lane == 31) wsum[wid] = x;
    __syncthreads();
    if (tid == 0) {
        int run = 0;
#pragma unroll
        for (int w = 0; w < 8; w++) { int t = wsum[w]; wsum[w] = run; run += t; }
        sbase = atomicAdd(&g_total, run);
    }
    __syncthreads();
    int run = sbase + wsum[wid] + (x - local);
#pragma unroll
    for (int j = 0; j < 4; j++) {
        if (base + j < ntot) { g_off[base + j] = run; g_cur[base + j] = run; }
        run += v[j];
    }
}

// ------------------------- scatter src ids into buckets ----------------------
__global__ void scatter_kernel(const int* __restrict__ ps, const int* __restrict__ pd,
                               const int* __restrict__ ns, const int* __restrict__ nd,
                               int e) {
    int i = blockIdx.x * blockDim.x + threadIdx.x;
    if (i == 0) g_total = 0;
    if (i >= 2 * e) return;
    int sign = (i >= e);
    int j = sign ? i - e : i;
    int s = sign ? ns[j] : ps[j];
    int d = sign ? nd[j] : pd[j];
    int pos = atomicAdd(&g_cur[sign * NNODES + d], 1);
    g_srcs[pos] = s;
}

// ------------------------- CSR aggregation (half-warp per segment) -----------
__global__ __launch_bounds__(256)
void aggregate_kernel(float* __restrict__ out,
                      const float* __restrict__ b_pos,
                      const float* __restrict__ b_neg, int n) {
    int warp = (blockIdx.x * blockDim.x + threadIdx.x) >> 5;
    int lane = threadIdx.x & 31;
    int half = lane >> 4;
    int l16  = lane & 15;
    int segi = warp * 2 + half;
    if (segi >= 2 * n) return;
    int sign = (segi >= n);
    int d = sign ? segi - n : segi;
    int seg = sign * NNODES + d;
    int h = l16 >> 1;

    float er_h = g_er[(size_t)sign * NNODES * HEADS + (size_t)d * HEADS + h];
    const float* elb = g_el + (size_t)sign * NNODES * HEADS;
    const __half* fb = g_feat16 + (size_t)sign * NNODES * HIDDEN;

    int start = g_off[seg];
    int end   = g_cur[seg];

    float acc[8] = {};
    float den = 0.f;

#define ACC8(r, ex) do {                                                       \
        float2 t;                                                              \
        t = __half22float2(*(__half2*)&(r).x);                                 \
        acc[0] = fmaf((ex), t.x, acc[0]); acc[1] = fmaf((ex), t.y, acc[1]);    \
        t = __half22float2(*(__half2*)&(r).y);                                 \
        acc[2] = fmaf((ex), t.x, acc[2]); acc[3] = fmaf((ex), t.y, acc[3]);    \
        t = __half22float2(*(__half2*)&(r).z);                                 \
        acc[4] = fmaf((ex), t.x, acc[4]); acc[5] = fmaf((ex), t.y, acc[5]);    \
        t = __half22float2(*(__half2*)&(r).w);                                 \
        acc[6] = fmaf((ex), t.x, acc[6]); acc[7] = fmaf((ex), t.y, acc[7]);    \
    } while (0)

    int k = start;
    for (; k + 1 < end; k += 2) {
        int s0 = g_srcs[k];
        int s1 = g_srcs[k + 1];
        float eh0 = elb[(size_t)s0 * HEADS + h] + er_h;
        float eh1 = elb[(size_t)s1 * HEADS + h] + er_h;
        uint4 r0 = *(const uint4*)&fb[(size_t)s0 * HIDDEN + l16 * 8];
        uint4 r1 = *(const uint4*)&fb[(size_t)s1 * HIDDEN + l16 * 8];
        eh0 = (eh0 > 0.f) ? eh0 : NEG_SLOPE * eh0;
        eh1 = (eh1 > 0.f) ? eh1 : NEG_SLOPE * eh1;
        float ex0 = __expf(eh0);
        float ex1 = __expf(eh1);
        den += ex0 + ex1;
        ACC8(r0, ex0);
        ACC8(r1, ex1);
    }
    if (k < end) {
        int s = g_srcs[k];
        float eh = elb[(size_t)s * HEADS + h] + er_h;
        eh = (eh > 0.f) ? eh : NEG_SLOPE * eh;
        float ex = __expf(eh);
        den += ex;
        uint4 r = *(const uint4*)&fb[(size_t)s * HIDDEN + l16 * 8];
        ACC8(r, ex);
    }
#undef ACC8

    float inv = (den > 0.f) ? (1.0f / den) : 0.0f;
    const float* bias = sign ? b_neg : b_pos;
    float* orow = &out[((size_t)sign * n + d) * HIDDEN + l16 * 8];
    float4 o0, o1;
    const float4 bv0 = *(const float4*)(bias + l16 * 8);
    const float4 bv1 = *(const float4*)(bias + l16 * 8 + 4);
    o0.x = acc[0] * inv + bv0.x; o0.y = acc[1] * inv + bv0.y;
    o0.z = acc[2] * inv + bv0.z; o0.w = acc[3] * inv + bv0.w;
    o1.x = acc[4] * inv + bv1.x; o1.y = acc[5] * inv + bv1.y;
    o1.z = acc[6] * inv + bv1.z; o1.w = acc[7] * inv + bv1.w;
    *(float4*)orow = o0;
    *(float4*)(orow + 4) = o1;
}

// ------------------------- fp16 helpers --------------------------------------
__device__ __forceinline__ uint32_t f2h2(float lo, float hi) {
    __half2 h = __floats2half2_rn(lo, hi);
    return *(uint32_t*)&h;
}

#define MMA_F16(cr, a, b)                                                      \
    asm volatile("mma.sync.aligned.m16n8k16.row.col.f32.f16.f16.f32 "          \
                 "{%0,%1,%2,%3},{%4,%5,%6,%7},{%8,%9},{%0,%1,%2,%3};"          \
                 : "+f"((cr)[0]), "+f"((cr)[1]), "+f"((cr)[2]), "+f"((cr)[3])  \
                 : "r"((a)[0]), "r"((a)[1]), "r"((a)[2]), "r"((a)[3]),         \
                   "r"((b)[0]), "r"((b)[1]))

// ldmatrix x4: loads the full m16k16 fp16 A fragment (a0..a3) in one op.
// Lane groups 0-7/8-15/16-23/24-31 supply rows for (mlow,klow)/(mhigh,klow)/
// (mlow,khigh)/(mhigh,khigh); matches mma.m16n8k16 A layout.
__device__ __forceinline__ void ldsm_x4(uint32_t* r, const uint32_t* ptr) {
    uint32_t addr = (uint32_t)__cvta_generic_to_shared(ptr);
    asm volatile("ldmatrix.sync.aligned.m8n8.x4.shared.b16 {%0,%1,%2,%3}, [%4];"
                 : "=r"(r[0]), "=r"(r[1]), "=r"(r[2]), "=r"(r[3]) : "r"(addr));
}

// ------------------------- tensor-core fp16 GEMM (feature pass) --------------
__global__ __launch_bounds__(256, 2)
void gemm_feat(const float* __restrict__ A0, int M, int K,
               const float* __restrict__ B0, const float* __restrict__ B1,
               __half* __restrict__ C0, __half* __restrict__ C1,
               const float* __restrict__ al0, const float* __restrict__ ar0,
               float* __restrict__ el0, float* __restrict__ er0,
               const float* __restrict__ al1, const float* __restrict__ ar1,
               float* __restrict__ el1, float* __restrict__ er1) {
    constexpr int NT = 128;
    constexpr int ASTR = 12;
    constexpr int BSTR = NT + 8;
    constexpr int WN   = NT / 2;
    constexpr int NJ   = WN / 8;
    constexpr int ASZ  = 128 * ASTR;
    constexpr int BSZ  = 8 * BSTR;

    __shared__ __align__(16) uint32_t As[2 * ASZ];
    __shared__ __align__(16) uint32_t Bs[2 * BSZ];

    const float* B  = B0;
    __half*      C  = C0;
    const float* al = al0; const float* ar = ar0;
    float*       el = el0; float*       er = er0;
    if (blockIdx.y == 1) { B = B1; C = C1; al = al1; ar = ar1; el = el1; er = er1; }

    const int tid  = threadIdx.x;
    const int wid  = tid >> 5;
    const int lane = tid & 31;
    const int g    = lane >> 2;
    const int tig  = lane & 3;
    const int wm   = wid & 3;
    const int wn   = wid >> 2;
    const int m0   = blockIdx.x * 128;
    // ldmatrix per-lane source row/col within the 16x16 A tile
    const int lrow = lane & 7;
    const int quad = lane >> 3;
    const int lm_roff = ((quad & 1) << 3) + lrow;   // row offset within m16
    const int lm_coff = (quad & 2) << 1;            // kpair offset: 0 or 4

    float c[2][NJ][4];
#pragma unroll
    for (int mi = 0; mi < 2; mi++)
#pragma unroll
        for (int nj = 0; nj < NJ; nj++)
#pragma unroll
            for (int q = 0; q < 4; q++) c[mi][nj][q] = 0.0f;

    float4 pa[2], pb[2];

#define LOAD_A(k0, i, dstv) do {                                               \
        int idx = tid + (i) * 256;                                             \
        int row = idx >> 2; int kk = (idx & 3) * 4;                            \
        int grow = m0 + row;                                                   \
        if (grow < M) {                                                        \
            dstv = *(const float4*)(A0 + (size_t)grow * 128 + (k0) + kk);      \
        } else dstv = make_float4(0.f, 0.f, 0.f, 0.f);                         \
    } while (0)
#define LOAD_B(k0) do {                                                        \
        int kp = tid >> 5, n4 = (tid & 31) * 4;                                \
        pb[0] = *(const float4*)(B + (size_t)((k0) + 2 * kp)     * NT + n4);   \
        pb[1] = *(const float4*)(B + (size_t)((k0) + 2 * kp + 1) * NT + n4);   \
    } while (0)
#define COMMIT(p) do {                                                         \
        _Pragma("unroll")                                                      \
        for (int i = 0; i < 2; i++) {                                          \
            int idx = tid + i * 256;                                           \
            int row = idx >> 2; int kp0 = (idx & 3) * 2;                       \
            uint2 t = make_uint2(f2h2(pa[i].x, pa[i].y), f2h2(pa[i].z, pa[i].w)); \
            *(uint2*)&As[(p) * ASZ + row * ASTR + kp0] = t;                    \
        }                                                                      \
        {                                                                      \
            int kp = tid >> 5, n4 = (tid & 31) * 4;                            \
            uint4 t = make_uint4(f2h2(pb[0].x, pb[1].x), f2h2(pb[0].y, pb[1].y), \
                                 f2h2(pb[0].z, pb[1].z), f2h2(pb[0].w, pb[1].w)); \
            *(uint4*)&Bs[(p) * BSZ + kp * BSTR + n4] = t;                      \
        }                                                                      \
    } while (0)

    LOAD_A(0, 0, pa[0]); LOAD_A(0, 1, pa[1]);
    LOAD_B(0);
    COMMIT(0);
    __syncthreads();
    if (K > 16) {
        LOAD_A(16, 0, pa[0]); LOAD_A(16, 1, pa[1]);
        LOAD_B(16);
    }

    int p = 0;
    for (int k0 = 0; k0 < K; k0 += 16) {
        if (k0 + 16 < K) {
            COMMIT(p ^ 1);
            if (k0 + 32 < K) {
                LOAD_A(k0 + 32, 0, pa[0]); LOAD_A(k0 + 32, 1, pa[1]);
                LOAD_B(k0 + 32);
            }
        }
        const uint32_t* Ap = &As[p * ASZ];
        const uint32_t* Bp = &Bs[p * BSZ];
        uint32_t af[2][4];
#pragma unroll
        for (int mi = 0; mi < 2; mi++) {
            int mb = wm * 32 + mi * 16;
            ldsm_x4(af[mi], &Ap[(mb + lm_roff) * ASTR + lm_coff]);
        }
        uint32_t bf[NJ][2];
#pragma unroll
        for (int nj = 0; nj < NJ; nj++) {
            int nb = wn * WN + nj * 8;
            bf[nj][0] = Bp[tig       * BSTR + nb + g];
            bf[nj][1] = Bp[(tig + 4) * BSTR + nb + g];
        }
#pragma unroll
        for (int mi = 0; mi < 2; mi++)
#pragma unroll
            for (int nj = 0; nj < NJ; nj++)
                MMA_F16(c[mi][nj], af[mi], bf[nj]);
        __syncthreads();
        p ^= 1;
    }
#undef LOAD_A
#undef LOAD_B
#undef COMMIT

    // ---- fused el/er epilogue ----
#pragma unroll
    for (int mi = 0; mi < 2; mi++) {
#pragma unroll
        for (int h = 0; h < 4; h++) {
            float e0 = 0.f, e1 = 0.f, r0v = 0.f, r1v = 0.f;
#pragma unroll
            for (int q = 0; q < 2; q++) {
                int nj = 2 * h + q;
                int col = wn * 64 + nj * 8 + 2 * tig;
                float a0 = al[col], a1 = al[col + 1];
                float b0 = ar[col], b1 = ar[col + 1];
                e0  += c[mi][nj][0] * a0 + c[mi][nj][1] * a1;
                e1  += c[mi][nj][2] * a0 + c[mi][nj][3] * a1;
                r0v += c[mi][nj][0] * b0 + c[mi][nj][1] * b1;
                r1v += c[mi][nj][2] * b0 + c[mi][nj][3] * b1;
            }
            e0  += __shfl_xor_sync(0xffffffffu, e0, 1);
            e0  += __shfl_xor_sync(0xffffffffu, e0, 2);
            e1  += __shfl_xor_sync(0xffffffffu, e1, 1);
            e1  += __shfl_xor_sync(0xffffffffu, e1, 2);
            r0v += __shfl_xor_sync(0xffffffffu, r0v, 1);
            r0v += __shfl_xor_sync(0xffffffffu, r0v, 2);
            r1v += __shfl_xor_sync(0xffffffffu, r1v, 1);
            r1v += __shfl_xor_sync(0xffffffffu, r1v, 2);
            if (tig == 0) {
                int hg = wn * 4 + h;
                int ra = m0 + wm * 32 + mi * 16 + g;
                int rb = ra + 8;
                if (ra < M) { el[ra * HEADS + hg] = e0;  er[ra * HEADS + hg] = r0v; }
                if (rb < M) { el[rb * HEADS + hg] = e1;  er[rb * HEADS + hg] = r1v; }
            }
        }
    }

    // ---- store C (fp16) ----
#pragma unroll
    for (int mi = 0; mi < 2; mi++) {
        int ra = m0 + wm * 32 + mi * 16 + g;
        int rb = ra + 8;
#pragma unroll
        for (int nj = 0; nj < NJ; nj++) {
            int col = wn * WN + nj * 8 + 2 * tig;
            if (ra < M) *(__half2*)&C[(size_t)ra * NT + col] =
                __floats2half2_rn(c[mi][nj][0], c[mi][nj][1]);
            if (rb < M) *(__half2*)&C[(size_t)rb * NT + col] =
                __floats2half2_rn(c[mi][nj][2], c[mi][nj][3]);
        }
    }
}

// ------------------------- fused MLP kernel ----------------------------------
// h_final[M,64] = relu([h_pos|h_neg][M,256] @ W1[256,128] + b1) @ W2[128,64] + b2
__global__ __launch_bounds__(256, 2)
void mlp_fused(const float* __restrict__ A0, const float* __restrict__ A1,
               int M,
               const float* __restrict__ W1, const float* __restrict__ b1,
               const float* __restrict__ W2, const float* __restrict__ b2,
               float* __restrict__ outF) {
    constexpr int NT = 128;
    constexpr int ASTR = 12;
    constexpr int BSTR = NT + 8;
    constexpr int NJ   = 8;
    constexpr int ASZ  = 128 * ASTR;
    constexpr int BSZ  = 8 * BSTR;
    __shared__ __align__(16) uint32_t smem[12288];
    uint32_t* As  = smem;
    uint32_t* Bs  = smem + 2 * ASZ;
    uint32_t* Hs  = smem;              // stage2: [128][64]
    uint32_t* B2s = smem + 8192;       // stage2: [64][64]

    const int tid  = threadIdx.x;
    const int wid  = tid >> 5;
    const int lane = tid & 31;
    const int g    = lane >> 2;
    const int tig  = lane & 3;
    const int wm   = wid & 3;
    const int wn   = wid >> 2;
    const int m0   = blockIdx.x * 128;
    const int lrow = lane & 7;
    const int quad = lane >> 3;
    const int lm_roff = ((quad & 1) << 3) + lrow;
    const int lm_coff = (quad & 2) << 1;

    float c[2][NJ][4];
#pragma unroll
    for (int mi = 0; mi < 2; mi++)
#pragma unroll
        for (int nj = 0; nj < NJ; nj++)
#pragma unroll
            for (int q = 0; q < 4; q++) c[mi][nj][q] = 0.0f;

    float4 pa[2], pb[2];

#define LOAD_A(k0, i, dstv) do {                                               \
        int idx = tid + (i) * 256;                                             \
        int row = idx >> 2; int kk = (idx & 3) * 4;                            \
        int grow = m0 + row;                                                   \
        if (grow < M) {                                                        \
            int kg = (k0) + kk;                                                \
            const float* srcp = (kg < 128) ? (A0 + (size_t)grow * 128 + kg)    \
                                           : (A1 + (size_t)grow * 128 + (kg - 128)); \
            dstv = *(const float4*)srcp;                                       \
        } else dstv = make_float4(0.f, 0.f, 0.f, 0.f);                         \
    } while (0)
#define LOAD_B(k0) do {                                                        \
        int kp = tid >> 5, n4 = (tid & 31) * 4;                                \
        pb[0] = *(const float4*)(W1 + (size_t)((k0) + 2 * kp)     * NT + n4);  \
        pb[1] = *(const float4*)(W1 + (size_t)((k0) + 2 * kp + 1) * NT + n4);  \
    } while (0)
#define COMMIT(p) do {                                                         \
        _Pragma("unroll")                                                      \
        for (int i = 0; i < 2; i++) {                                          \
            int idx = tid + i * 256;                                           \
            int row = idx >> 2; int kp0 = (idx & 3) * 2;                       \
            uint2 t = make_uint2(f2h2(pa[i].x, pa[i].y), f2h2(pa[i].z, pa[i].w)); \
            *(uint2*)&As[(p) * ASZ + row * ASTR + kp0] = t;                    \
        }                                                                      \
        {                                                                      \
            int kp = tid >> 5, n4 = (tid & 31) * 4;                            \
            uint4 t = make_uint4(f2h2(pb[0].x, pb[1].x), f2h2(pb[0].y, pb[1].y), \
                                 f2h2(pb[0].z, pb[1].z), f2h2(pb[0].w, pb[1].w)); \
            *(uint4*)&Bs[(p) * BSZ + kp * BSTR + n4] = t;                      \
        }                                                                      \
    } while (0)

    LOAD_A(0, 0, pa[0]); LOAD_A(0, 1, pa[1]);
    LOAD_B(0);
    COMMIT(0);
    __syncthreads();
    LOAD_A(16, 0, pa[0]); LOAD_A(16, 1, pa[1]);
    LOAD_B(16);

    int p = 0;
    for (int k0 = 0; k0 < 256; k0 += 16) {
        if (k0 + 16 < 256) {
            COMMIT(p ^ 1);
            if (k0 + 32 < 256) {
                LOAD_A(k0 + 32, 0, pa[0]); LOAD_A(k0 + 32, 1, pa[1]);
                LOAD_B(k0 + 32);
            }
        }
        const uint32_t* Ap = &As[p * ASZ];
        const uint32_t* Bp = &Bs[p * BSZ];
        uint32_t af[2][4];
#pragma unroll
        for (int mi = 0; mi < 2; mi++) {
            int mb = wm * 32 + mi * 16;
            ldsm_x4(af[mi], &Ap[(mb + lm_roff) * ASTR + lm_coff]);
        }
        uint32_t bf[NJ][2];
#pragma unroll
        for (int nj = 0; nj < NJ; nj++) {
            int nb = wn * 64 + nj * 8;
            bf[nj][0] = Bp[tig       * BSTR + nb + g];
            bf[nj][1] = Bp[(tig + 4) * BSTR + nb + g];
        }
#pragma unroll
        for (int mi = 0; mi < 2; mi++)
#pragma unroll
            for (int nj = 0; nj < NJ; nj++)
                MMA_F16(c[mi][nj], af[mi], bf[nj]);
        __syncthreads();
        p ^= 1;
    }
#undef LOAD_A
#undef LOAD_B
#undef COMMIT

    // ---- write hidden (bias + relu, fp16) into Hs, swizzle kp ^ (g<<2) ----
#pragma unroll
    for (int mi = 0; mi < 2; mi++) {
        int ra = wm * 32 + mi * 16 + g;
        int rb = ra + 8;
#pragma unroll
        for (int nj = 0; nj < NJ; nj++) {
            int col = wn * 64 + nj * 8 + 2 * tig;
            float bx = b1[col], by = b1[col + 1];
            float v0 = fmaxf(c[mi][nj][0] + bx, 0.f);
            float v1 = fmaxf(c[mi][nj][1] + by, 0.f);
            float v2 = fmaxf(c[mi][nj][2] + bx, 0.f);
            float v3 = fmaxf(c[mi][nj][3] + by, 0.f);
            int cp = wn * 32 + nj * 4 + tig;
            Hs[ra * 64 + (cp ^ (g << 2))] = f2h2(v0, v1);
            Hs[rb * 64 + (cp ^ (g << 2))] = f2h2(v2, v3);
        }
    }

    // ---- load W2 [128,64] into B2s, swizzle n ^ ((kp&3)<<3) ----
#pragma unroll
    for (int i = 0; i < 4; i++) {
        int idx = tid + i * 256;
        int kp = idx >> 4;
        int n4 = (idx & 15) * 4;
        float4 ev = *(const float4*)(W2 + (size_t)(2 * kp)     * 64 + n4);
        float4 ov = *(const float4*)(W2 + (size_t)(2 * kp + 1) * 64 + n4);
        uint4 t = make_uint4(f2h2(ev.x, ov.x), f2h2(ev.y, ov.y),
                             f2h2(ev.z, ov.z), f2h2(ev.w, ov.w));
        *(uint4*)&B2s[kp * 64 + (n4 ^ ((kp & 3) << 3))] = t;
    }
    __syncthreads();

    // ---- stage 2: [128,128] @ [128,64], 8 k16 steps ----
    float c2[2][4][4];
#pragma unroll
    for (int mi = 0; mi < 2; mi++)
#pragma unroll
        for (int nj = 0; nj < 4; nj++)
#pragma unroll
            for (int q = 0; q < 4; q++) c2[mi][nj][q] = 0.0f;

#pragma unroll
    for (int ks8 = 0; ks8 < 8; ks8++) {
        int kp0 = ks8 * 8;
        uint32_t af[2][4];
#pragma unroll
        for (int mi = 0; mi < 2; mi++) {
            int mb = wm * 32 + mi * 16;
            af[mi][0] = Hs[(mb + g)     * 64 + ((kp0 + tig)     ^ (g << 2))];
            af[mi][1] = Hs[(mb + 8 + g) * 64 + ((kp0 + tig)     ^ (g << 2))];
            af[mi][2] = Hs[(mb + g)     * 64 + ((kp0 + tig + 4) ^ (g << 2))];
            af[mi][3] = Hs[(mb + 8 + g) * 64 + ((kp0 + tig + 4) ^ (g << 2))];
        }
        uint32_t bf[4][2];
#pragma unroll
        for (int nj = 0; nj < 4; nj++) {
            int nb = wn * 32 + nj * 8 + g;
            bf[nj][0] = B2s[(kp0 + tig)     * 64 + (nb ^ (tig << 3))];
            bf[nj][1] = B2s[(kp0 + tig + 4) * 64 + (nb ^ (tig << 3))];
        }
#pragma unroll
        for (int mi = 0; mi < 2; mi++)
#pragma unroll
            for (int nj = 0; nj < 4; nj++)
                MMA_F16(c2[mi][nj], af[mi], bf[nj]);
    }

    // ---- store h_final (fp32, + b2) ----
#pragma unroll
    for (int mi = 0; mi < 2; mi++) {
        int ra = m0 + wm * 32 + mi * 16 + g;
        int rb = ra + 8;
#pragma unroll
        for (int nj = 0; nj < 4; nj++) {
            int col = wn * 32 + nj * 8 + 2 * tig;
            float bx = b2[col], by = b2[col + 1];
            if (ra < M) *(float2*)&outF[(size_t)ra * 64 + col] =
                make_float2(c2[mi][nj][0] + bx, c2[mi][nj][1] + by);
            if (rb < M) *(float2*)&outF[(size_t)rb * 64 + col] =
                make_float2(c2[mi][nj][2] + bx, c2[mi][nj][3] + by);
        }
    }
}

// ------------------------- launcher ------------------------------------------
extern "C" void kernel_launch(void* const* d_in, const int* in_sizes, int n_in,
                              void* d_out, int out_size) {
    const float* features = (const float*)d_in[0];
    const int*   pos_src  = (const int*)d_in[1];
    const int*   pos_dst  = (const int*)d_in[2];
    const int*   neg_src  = (const int*)d_in[3];
    const int*   neg_dst  = (const int*)d_in[4];
    const float* W_pos    = (const float*)d_in[5];
    const float* al_pos   = (const float*)d_in[6];
    const float* ar_pos   = (const float*)d_in[7];
    const float* b_pos    = (const float*)d_in[8];
    const float* W_neg    = (const float*)d_in[9];
    const float* al_neg   = (const float*)d_in[10];
    const float* ar_neg   = (const float*)d_in[11];
    const float* b_neg    = (const float*)d_in[12];
    const float* W1       = (const float*)d_in[13];
    const float* b1       = (const float*)d_in[14];
    const float* W2       = (const float*)d_in[15];
    const float* b2       = (const float*)d_in[16];
    float* out = (float*)d_out;

    int n = in_sizes[0] / HIDDEN;   // 100000
    int e = in_sizes[1];            // 600000

    void* p;
    cudaGetSymbolAddress(&p, g_feat16); __half* featp = (__half*)p;
    cudaGetSymbolAddress(&p, g_el);     float*  elp   = (float*)p;
    cudaGetSymbolAddress(&p, g_er);     float*  erp   = (float*)p;

    float* h_pos   = out;
    float* h_neg   = out + (size_t)n * HIDDEN;
    float* h_final = out + (size_t)2 * n * HIDDEN;

    int gb   = (n + 127) / 128;
    int nseg = 2 * n;
    int nb   = (nseg + 1023) / 1024;

    // Fork a side stream for the CSR build (independent of the feature GEMMs).
    cudaStream_t s1;
    cudaEvent_t ev_fork, ev_join;
    cudaStreamCreateWithFlags(&s1, cudaStreamNonBlocking);
    cudaEventCreateWithFlags(&ev_fork, cudaEventDisableTiming);
    cudaEventCreateWithFlags(&ev_join, cudaEventDisableTiming);

    cudaEventRecord(ev_fork, 0);
    cudaStreamWaitEvent(s1, ev_fork, 0);

    // --- side stream: CSR build (3 kernels; g_cnt/g_total self-reinitializing) ---
    hist_kernel<<<(2 * e + 255) / 256, 256, 0, s1>>>(pos_dst, neg_dst, e);
    scan_fused<<<nb, 256, 0, s1>>>(nseg);
    scatter_kernel<<<(2 * e + 255) / 256, 256, 0, s1>>>(pos_src, pos_dst, neg_src, neg_dst, e);
    cudaEventRecord(ev_join, s1);

    // --- main stream: feature transform GEMMs (fp16 MMA, both signs) ---
    {
        dim3 grid(gb, 2);
        gemm_feat<<<grid, 256>>>(
            features, n, HIDDEN,
            W_pos, W_neg,
            featp, featp + (size_t)NNODES * HIDDEN,
            al_pos, ar_pos, elp, erp,
            al_neg, ar_neg,
            elp + (size_t)NNODES * HEADS, erp + (size_t)NNODES * HEADS);
    }

    // join: aggregation needs both CSR and features
    cudaStreamWaitEvent(0, ev_join, 0);

    // --- fused softmax + aggregation + normalize + bias (h_pos | h_neg) ---
    {
        int nwarps = (2 * n + 1) / 2;            // half-warp per segment
        int gwb = (nwarps + 7) / 8;              // 8 warps per 256-thread block
        aggregate_kernel<<<gwb, 256>>>(out, b_pos, b_neg, n);
    }

    // --- fused MLP: h_final = relu([h_pos|h_neg] @ W1 + b1) @ W2 + b2 ---
    mlp_fused<<<gb, 256>>>(h_pos, h_neg, n, W1, b1, W2, b2, h_final);
}

// round 16
// speedup vs baseline: 1.3460x; 1.0166x over previous
#include <cuda_runtime.h>
#include <cuda_fp16.h>
#include <cstdint>

#define NNODES 100000
#define NEDGES 600000
#define HIDDEN 128
#define HEADS  8
#define DH     16
#define NEG_SLOPE 0.2f
#define NSEG (2 * NNODES)            // (sign, node) segments

// ------------------------- scratch (static device globals) -------------------
__device__ __half g_feat16[2 * NNODES * HIDDEN]; // transformed features (fp16), per sign
__device__ float g_el  [2 * NNODES * HEADS];
__device__ float g_er  [2 * NNODES * HEADS];
__device__ int   g_cnt [NSEG];                  // per-seg in-degree (self-zeroing)
__device__ int   g_off [NSEG];                  // segment start offsets
__device__ int   g_cur [NSEG];                  // scatter cursors (end after scatter)
__device__ int   g_total;                       // block-base allocator (self-zeroing)
__device__ int   g_srcs[2 * NEDGES];            // src ids, bucketed by (sign,dst)

// ------------------------- histogram of dst ----------------------------------
__global__ void hist_kernel(const int* __restrict__ pd, const int* __restrict__ nd,
                            int e) {
    int i = blockIdx.x * blockDim.x + threadIdx.x;
    if (i >= 2 * e) return;
    int sign = (i >= e);
    int d = sign ? nd[i - e] : pd[i];
    atomicAdd(&g_cnt[sign * NNODES + d], 1);
}

// ------------------------- fused allocator scan ------------------------------
__global__ __launch_bounds__(256)
void scan_fused(int ntot) {
    __shared__ int wsum[8];
    __shared__ int sbase;
    int tid = threadIdx.x;
    int lane = tid & 31, wid = tid >> 5;
    int base = blockIdx.x * 1024 + tid * 4;
    int v[4];
#pragma unroll
    for (int j = 0; j < 4; j++)
        v[j] = (base + j < ntot) ? g_cnt[base + j] : 0;
#pragma unroll
    for (int j = 0; j < 4; j++)
        if (base + j < ntot) g_cnt[base + j] = 0;
    int local = v[0] + v[1] + v[2] + v[3];
    int x = local;
#pragma unroll
    for (int o = 1; o < 32; o <<= 1) {
        int t = __shfl_up_sync(0xffffffffu, x, o);
        if (lane >= o) x += t;
    }
    if (lane == 31) wsum[wid] = x;
    __syncthreads();
    if (tid == 0) {
        int run = 0;
#pragma unroll
        for (int w = 0; w < 8; w++) { int t = wsum[w]; wsum[w] = run; run += t; }
        sbase = atomicAdd(&g_total, run);
    }
    __syncthreads();
    int run = sbase + wsum[wid] + (x - local);
#pragma unroll
    for (int j = 0; j < 4; j++) {
        if (base + j < ntot) { g_off[base + j] = run; g_cur[base + j] = run; }
        run += v[j];
    }
}

// ------------------------- scatter src ids into buckets ----------------------
__global__ void scatter_kernel(const int* __restrict__ ps, const int* __restrict__ pd,
                               const int* __restrict__ ns, const int* __restrict__ nd,
                               int e) {
    int i = blockIdx.x * blockDim.x + threadIdx.x;
    if (i == 0) g_total = 0;
    if (i >= 2 * e) return;
    int sign = (i >= e);
    int j = sign ? i - e : i;
    int s = sign ? ns[j] : ps[j];
    int d = sign ? nd[j] : pd[j];
    int pos = atomicAdd(&g_cur[sign * NNODES + d], 1);
    g_srcs[pos] = s;
}

// ------------------------- CSR aggregation (half-warp per segment) -----------
// 4-wide unrolled: 4 independent src/el/feature gather chains in flight.
__global__ __launch_bounds__(256)
void aggregate_kernel(float* __restrict__ out,
                      const float* __restrict__ b_pos,
                      const float* __restrict__ b_neg, int n) {
    int warp = (blockIdx.x * blockDim.x + threadIdx.x) >> 5;
    int lane = threadIdx.x & 31;
    int half = lane >> 4;
    int l16  = lane & 15;
    int segi = warp * 2 + half;
    if (segi >= 2 * n) return;
    int sign = (segi >= n);
    int d = sign ? segi - n : segi;
    int seg = sign * NNODES + d;
    int h = l16 >> 1;

    float er_h = g_er[(size_t)sign * NNODES * HEADS + (size_t)d * HEADS + h];
    const float* elb = g_el + (size_t)sign * NNODES * HEADS;
    const __half* fb = g_feat16 + (size_t)sign * NNODES * HIDDEN;

    int start = g_off[seg];
    int end   = g_cur[seg];

    float acc[8] = {};
    float den = 0.f;

#define ACC8(r, ex) do {                                                       \
        float2 t;                                                              \
        t = __half22float2(*(__half2*)&(r).x);                                 \
        acc[0] = fmaf((ex), t.x, acc[0]); acc[1] = fmaf((ex), t.y, acc[1]);    \
        t = __half22float2(*(__half2*)&(r).y);                                 \
        acc[2] = fmaf((ex), t.x, acc[2]); acc[3] = fmaf((ex), t.y, acc[3]);    \
        t = __half22float2(*(__half2*)&(r).z);                                 \
        acc[4] = fmaf((ex), t.x, acc[4]); acc[5] = fmaf((ex), t.y, acc[5]);    \
        t = __half22float2(*(__half2*)&(r).w);                                 \
        acc[6] = fmaf((ex), t.x, acc[6]); acc[7] = fmaf((ex), t.y, acc[7]);    \
    } while (0)

    int k = start;
    // 4-wide: all 4 src loads, then 4 el loads, then 4 feature gathers issued
    // back-to-back before any consumption -> MLP ~8 outstanding loads.
    for (; k + 3 < end; k += 4) {
        int s0 = g_srcs[k];
        int s1 = g_srcs[k + 1];
        int s2 = g_srcs[k + 2];
        int s3 = g_srcs[k + 3];
        float e0 = elb[(size_t)s0 * HEADS + h];
        float e1 = elb[(size_t)s1 * HEADS + h];
        float e2 = elb[(size_t)s2 * HEADS + h];
        float e3 = elb[(size_t)s3 * HEADS + h];
        uint4 r0 = *(const uint4*)&fb[(size_t)s0 * HIDDEN + l16 * 8];
        uint4 r1 = *(const uint4*)&fb[(size_t)s1 * HIDDEN + l16 * 8];
        uint4 r2 = *(const uint4*)&fb[(size_t)s2 * HIDDEN + l16 * 8];
        uint4 r3 = *(const uint4*)&fb[(size_t)s3 * HIDDEN + l16 * 8];
        e0 += er_h; e1 += er_h; e2 += er_h; e3 += er_h;
        e0 = (e0 > 0.f) ? e0 : NEG_SLOPE * e0;
        e1 = (e1 > 0.f) ? e1 : NEG_SLOPE * e1;
        e2 = (e2 > 0.f) ? e2 : NEG_SLOPE * e2;
        e3 = (e3 > 0.f) ? e3 : NEG_SLOPE * e3;
        float x0 = __expf(e0);
        float x1 = __expf(e1);
        float x2 = __expf(e2);
        float x3 = __expf(e3);
        den += (x0 + x1) + (x2 + x3);
        ACC8(r0, x0);
        ACC8(r1, x1);
        ACC8(r2, x2);
        ACC8(r3, x3);
    }
    for (; k + 1 < end; k += 2) {
        int s0 = g_srcs[k];
        int s1 = g_srcs[k + 1];
        float e0 = elb[(size_t)s0 * HEADS + h] + er_h;
        float e1 = elb[(size_t)s1 * HEADS + h] + er_h;
        uint4 r0 = *(const uint4*)&fb[(size_t)s0 * HIDDEN + l16 * 8];
        uint4 r1 = *(const uint4*)&fb[(size_t)s1 * HIDDEN + l16 * 8];
        e0 = (e0 > 0.f) ? e0 : NEG_SLOPE * e0;
        e1 = (e1 > 0.f) ? e1 : NEG_SLOPE * e1;
        float x0 = __expf(e0);
        float x1 = __expf(e1);
        den += x0 + x1;
        ACC8(r0, x0);
        ACC8(r1, x1);
    }
    if (k < end) {
        int s = g_srcs[k];
        float eh = elb[(size_t)s * HEADS + h] + er_h;
        eh = (eh > 0.f) ? eh : NEG_SLOPE * eh;
        float ex = __expf(eh);
        den += ex;
        uint4 r = *(const uint4*)&fb[(size_t)s * HIDDEN + l16 * 8];
        ACC8(r, ex);
    }
#undef ACC8

    float inv = (den > 0.f) ? (1.0f / den) : 0.0f;
    const float* bias = sign ? b_neg : b_pos;
    float* orow = &out[((size_t)sign * n + d) * HIDDEN + l16 * 8];
    float4 o0, o1;
    const float4 bv0 = *(const float4*)(bias + l16 * 8);
    const float4 bv1 = *(const float4*)(bias + l16 * 8 + 4);
    o0.x = acc[0] * inv + bv0.x; o0.y = acc[1] * inv + bv0.y;
    o0.z = acc[2] * inv + bv0.z; o0.w = acc[3] * inv + bv0.w;
    o1.x = acc[4] * inv + bv1.x; o1.y = acc[5] * inv + bv1.y;
    o1.z = acc[6] * inv + bv1.z; o1.w = acc[7] * inv + bv1.w;
    *(float4*)orow = o0;
    *(float4*)(orow + 4) = o1;
}

// ------------------------- fp16 helpers --------------------------------------
__device__ __forceinline__ uint32_t f2h2(float lo, float hi) {
    __half2 h = __floats2half2_rn(lo, hi);
    return *(uint32_t*)&h;
}

#define MMA_F16(cr, a, b)                                                      \
    asm volatile("mma.sync.aligned.m16n8k16.row.col.f32.f16.f16.f32 "          \
                 "{%0,%1,%2,%3},{%4,%5,%6,%7},{%8,%9},{%0,%1,%2,%3};"          \
                 : "+f"((cr)[0]), "+f"((cr)[1]), "+f"((cr)[2]), "+f"((cr)[3])  \
                 : "r"((a)[0]), "r"((a)[1]), "r"((a)[2]), "r"((a)[3]),         \
                   "r"((b)[0]), "r"((b)[1]))

// ldmatrix x4: loads the full m16k16 fp16 A fragment (a0..a3) in one op.
__device__ __forceinline__ void ldsm_x4(uint32_t* r, const uint32_t* ptr) {
    uint32_t addr = (uint32_t)__cvta_generic_to_shared(ptr);
    asm volatile("ldmatrix.sync.aligned.m8n8.x4.shared.b16 {%0,%1,%2,%3}, [%4];"
                 : "=r"(r[0]), "=r"(r[1]), "=r"(r[2]), "=r"(r[3]) : "r"(addr));
}

// ------------------------- tensor-core fp16 GEMM (feature pass) --------------
__global__ __launch_bounds__(256, 2)
void gemm_feat(const float* __restrict__ A0, int M, int K,
               const float* __restrict__ B0, const float* __restrict__ B1,
               __half* __restrict__ C0, __half* __restrict__ C1,
               const float* __restrict__ al0, const float* __restrict__ ar0,
               float* __restrict__ el0, float* __restrict__ er0,
               const float* __restrict__ al1, const float* __restrict__ ar1,
               float* __restrict__ el1, float* __restrict__ er1) {
    constexpr int NT = 128;
    constexpr int ASTR = 12;
    constexpr int BSTR = NT + 8;
    constexpr int WN   = NT / 2;
    constexpr int NJ   = WN / 8;
    constexpr int ASZ  = 128 * ASTR;
    constexpr int BSZ  = 8 * BSTR;

    __shared__ __align__(16) uint32_t As[2 * ASZ];
    __shared__ __align__(16) uint32_t Bs[2 * BSZ];

    const float* B  = B0;
    __half*      C  = C0;
    const float* al = al0; const float* ar = ar0;
    float*       el = el0; float*       er = er0;
    if (blockIdx.y == 1) { B = B1; C = C1; al = al1; ar = ar1; el = el1; er = er1; }

    const int tid  = threadIdx.x;
    const int wid  = tid >> 5;
    const int lane = tid & 31;
    const int g    = lane >> 2;
    const int tig  = lane & 3;
    const int wm   = wid & 3;
    const int wn   = wid >> 2;
    const int m0   = blockIdx.x * 128;
    const int lrow = lane & 7;
    const int quad = lane >> 3;
    const int lm_roff = ((quad & 1) << 3) + lrow;
    const int lm_coff = (quad & 2) << 1;

    float c[2][NJ][4];
#pragma unroll
    for (int mi = 0; mi < 2; mi++)
#pragma unroll
        for (int nj = 0; nj < NJ; nj++)
#pragma unroll
            for (int q = 0; q < 4; q++) c[mi][nj][q] = 0.0f;

    float4 pa[2], pb[2];

#define LOAD_A(k0, i, dstv) do {                                               \
        int idx = tid + (i) * 256;                                             \
        int row = idx >> 2; int kk = (idx & 3) * 4;                            \
        int grow = m0 + row;                                                   \
        if (grow < M) {                                                        \
            dstv = *(const float4*)(A0 + (size_t)grow * 128 + (k0) + kk);      \
        } else dstv = make_float4(0.f, 0.f, 0.f, 0.f);                         \
    } while (0)
#define LOAD_B(k0) do {                                                        \
        int kp = tid >> 5, n4 = (tid & 31) * 4;                                \
        pb[0] = *(const float4*)(B + (size_t)((k0) + 2 * kp)     * NT + n4);   \
        pb[1] = *(const float4*)(B + (size_t)((k0) + 2 * kp + 1) * NT + n4);   \
    } while (0)
#define COMMIT(p) do {                                                         \
        _Pragma("unroll")                                                      \
        for (int i = 0; i < 2; i++) {                                          \
            int idx = tid + i * 256;                                           \
            int row = idx >> 2; int kp0 = (idx & 3) * 2;                       \
            uint2 t = make_uint2(f2h2(pa[i].x, pa[i].y), f2h2(pa[i].z, pa[i].w)); \
            *(uint2*)&As[(p) * ASZ + row * ASTR + kp0] = t;                    \
        }                                                                      \
        {                                                                      \
            int kp = tid >> 5, n4 = (tid & 31) * 4;                            \
            uint4 t = make_uint4(f2h2(pb[0].x, pb[1].x), f2h2(pb[0].y, pb[1].y), \
                                 f2h2(pb[0].z, pb[1].z), f2h2(pb[0].w, pb[1].w)); \
            *(uint4*)&Bs[(p) * BSZ + kp * BSTR + n4] = t;                      \
        }                                                                      \
    } while (0)

    LOAD_A(0, 0, pa[0]); LOAD_A(0, 1, pa[1]);
    LOAD_B(0);
    COMMIT(0);
    __syncthreads();
    if (K > 16) {
        LOAD_A(16, 0, pa[0]); LOAD_A(16, 1, pa[1]);
        LOAD_B(16);
    }

    int p = 0;
    for (int k0 = 0; k0 < K; k0 += 16) {
        if (k0 + 16 < K) {
            COMMIT(p ^ 1);
            if (k0 + 32 < K) {
                LOAD_A(k0 + 32, 0, pa[0]); LOAD_A(k0 + 32, 1, pa[1]);
                LOAD_B(k0 + 32);
            }
        }
        const uint32_t* Ap = &As[p * ASZ];
        const uint32_t* Bp = &Bs[p * BSZ];
        uint32_t af[2][4];
#pragma unroll
        for (int mi = 0; mi < 2; mi++) {
            int mb = wm * 32 + mi * 16;
            ldsm_x4(af[mi], &Ap[(mb + lm_roff) * ASTR + lm_coff]);
        }
        uint32_t bf[NJ][2];
#pragma unroll
        for (int nj = 0; nj < NJ; nj++) {
            int nb = wn * WN + nj * 8;
            bf[nj][0] = Bp[tig       * BSTR + nb + g];
            bf[nj][1] = Bp[(tig + 4) * BSTR + nb + g];
        }
#pragma unroll
        for (int mi = 0; mi < 2; mi++)
#pragma unroll
            for (int nj = 0; nj < NJ; nj++)
                MMA_F16(c[mi][nj], af[mi], bf[nj]);
        __syncthreads();
        p ^= 1;
    }
#undef LOAD_A
#undef LOAD_B
#undef COMMIT

    // ---- fused el/er epilogue ----
#pragma unroll
    for (int mi = 0; mi < 2; mi++) {
#pragma unroll
        for (int h = 0; h < 4; h++) {
            float e0 = 0.f, e1 = 0.f, r0v = 0.f, r1v = 0.f;
#pragma unroll
            for (int q = 0; q < 2; q++) {
                int nj = 2 * h + q;
                int col = wn * 64 + nj * 8 + 2 * tig;
                float a0 = al[col], a1 = al[col + 1];
                float b0 = ar[col], b1 = ar[col + 1];
                e0  += c[mi][nj][0] * a0 + c[mi][nj][1] * a1;
                e1  += c[mi][nj][2] * a0 + c[mi][nj][3] * a1;
                r0v += c[mi][nj][0] * b0 + c[mi][nj][1] * b1;
                r1v += c[mi][nj][2] * b0 + c[mi][nj][3] * b1;
            }
            e0  += __shfl_xor_sync(0xffffffffu, e0, 1);
            e0  += __shfl_xor_sync(0xffffffffu, e0, 2);
            e1  += __shfl_xor_sync(0xffffffffu, e1, 1);
            e1  += __shfl_xor_sync(0xffffffffu, e1, 2);
            r0v += __shfl_xor_sync(0xffffffffu, r0v, 1);
            r0v += __shfl_xor_sync(0xffffffffu, r0v, 2);
            r1v += __shfl_xor_sync(0xffffffffu, r1v, 1);
            r1v += __shfl_xor_sync(0xffffffffu, r1v, 2);
            if (tig == 0) {
                int hg = wn * 4 + h;
                int ra = m0 + wm * 32 + mi * 16 + g;
                int rb = ra + 8;
                if (ra < M) { el[ra * HEADS + hg] = e0;  er[ra * HEADS + hg] = r0v; }
                if (rb < M) { el[rb * HEADS + hg] = e1;  er[rb * HEADS + hg] = r1v; }
            }
        }
    }

    // ---- store C (fp16) ----
#pragma unroll
    for (int mi = 0; mi < 2; mi++) {
        int ra = m0 + wm * 32 + mi * 16 + g;
        int rb = ra + 8;
#pragma unroll
        for (int nj = 0; nj < NJ; nj++) {
            int col = wn * WN + nj * 8 + 2 * tig;
            if (ra < M) *(__half2*)&C[(size_t)ra * NT + col] =
                __floats2half2_rn(c[mi][nj][0], c[mi][nj][1]);
            if (rb < M) *(__half2*)&C[(size_t)rb * NT + col] =
                __floats2half2_rn(c[mi][nj][2], c[mi][nj][3]);
        }
    }
}

// ------------------------- fused MLP kernel ----------------------------------
// h_final[M,64] = relu([h_pos|h_neg][M,256] @ W1[256,128] + b1) @ W2[128,64] + b2
__global__ __launch_bounds__(256, 2)
void mlp_fused(const float* __restrict__ A0, const float* __restrict__ A1,
               int M,
               const float* __restrict__ W1, const float* __restrict__ b1,
               const float* __restrict__ W2, const float* __restrict__ b2,
               float* __restrict__ outF) {
    constexpr int NT = 128;
    constexpr int ASTR = 12;
    constexpr int BSTR = NT + 8;
    constexpr int NJ   = 8;
    constexpr int ASZ  = 128 * ASTR;
    constexpr int BSZ  = 8 * BSTR;
    __shared__ __align__(16) uint32_t smem[12288];
    uint32_t* As  = smem;
    uint32_t* Bs  = smem + 2 * ASZ;
    uint32_t* Hs  = smem;              // stage2: [128][64]
    uint32_t* B2s = smem + 8192;       // stage2: [64][64]

    const int tid  = threadIdx.x;
    const int wid  = tid >> 5;
    const int lane = tid & 31;
    const int g    = lane >> 2;
    const int tig  = lane & 3;
    const int wm   = wid & 3;
    const int wn   = wid >> 2;
    const int m0   = blockIdx.x * 128;
    const int lrow = lane & 7;
    const int quad = lane >> 3;
    const int lm_roff = ((quad & 1) << 3) + lrow;
    const int lm_coff = (quad & 2) << 1;

    float c[2][NJ][4];
#pragma unroll
    for (int mi = 0; mi < 2; mi++)
#pragma unroll
        for (int nj = 0; nj < NJ; nj++)
#pragma unroll
            for (int q = 0; q < 4; q++) c[mi][nj][q] = 0.0f;

    float4 pa[2], pb[2];

#define LOAD_A(k0, i, dstv) do {                                               \
        int idx = tid + (i) * 256;                                             \
        int row = idx >> 2; int kk = (idx & 3) * 4;                            \
        int grow = m0 + row;                                                   \
        if (grow < M) {                                                        \
            int kg = (k0) + kk;                                                \
            const float* srcp = (kg < 128) ? (A0 + (size_t)grow * 128 + kg)    \
                                           : (A1 + (size_t)grow * 128 + (kg - 128)); \
            dstv = *(const float4*)srcp;                                       \
        } else dstv = make_float4(0.f, 0.f, 0.f, 0.f);                         \
    } while (0)
#define LOAD_B(k0) do {                                                        \
        int kp = tid >> 5, n4 = (tid & 31) * 4;                                \
        pb[0] = *(const float4*)(W1 + (size_t)((k0) + 2 * kp)     * NT + n4);  \
        pb[1] = *(const float4*)(W1 + (size_t)((k0) + 2 * kp + 1) * NT + n4);  \
    } while (0)
#define COMMIT(p) do {                                                         \
        _Pragma("unroll")                                                      \
        for (int i = 0; i < 2; i++) {                                          \
            int idx = tid + i * 256;                                           \
            int row = idx >> 2; int kp0 = (idx & 3) * 2;                       \
            uint2 t = make_uint2(f2h2(pa[i].x, pa[i].y), f2h2(pa[i].z, pa[i].w)); \
            *(uint2*)&As[(p) * ASZ + row * ASTR + kp0] = t;                    \
        }                                                                      \
        {                                                                      \
            int kp = tid >> 5, n4 = (tid & 31) * 4;                            \
            uint4 t = make_uint4(f2h2(pb[0].x, pb[1].x), f2h2(pb[0].y, pb[1].y), \
                                 f2h2(pb[0].z, pb[1].z), f2h2(pb[0].w, pb[1].w)); \
            *(uint4*)&Bs[(p) * BSZ + kp * BSTR + n4] = t;                      \
        }                                                                      \
    } while (0)

    LOAD_A(0, 0, pa[0]); LOAD_A(0, 1, pa[1]);
    LOAD_B(0);
    COMMIT(0);
    __syncthreads();
    LOAD_A(16, 0, pa[0]); LOAD_A(16, 1, pa[1]);
    LOAD_B(16);

    int p = 0;
    for (int k0 = 0; k0 < 256; k0 += 16) {
        if (k0 + 16 < 256) {
            COMMIT(p ^ 1);
            if (k0 + 32 < 256) {
                LOAD_A(k0 + 32, 0, pa[0]); LOAD_A(k0 + 32, 1, pa[1]);
                LOAD_B(k0 + 32);
            }
        }
        const uint32_t* Ap = &As[p * ASZ];
        const uint32_t* Bp = &Bs[p * BSZ];
        uint32_t af[2][4];
#pragma unroll
        for (int mi = 0; mi < 2; mi++) {
            int mb = wm * 32 + mi * 16;
            ldsm_x4(af[mi], &Ap[(mb + lm_roff) * ASTR + lm_coff]);
        }
        uint32_t bf[NJ][2];
#pragma unroll
        for (int nj = 0; nj < NJ; nj++) {
            int nb = wn * 64 + nj * 8;
            bf[nj][0] = Bp[tig       * BSTR + nb + g];
            bf[nj][1] = Bp[(tig + 4) * BSTR + nb + g];
        }
#pragma unroll
        for (int mi = 0; mi < 2; mi++)
#pragma unroll
            for (int nj = 0; nj < NJ; nj++)
                MMA_F16(c[mi][nj], af[mi], bf[nj]);
        __syncthreads();
        p ^= 1;
    }
#undef LOAD_A
#undef LOAD_B
#undef COMMIT

    // ---- write hidden (bias + relu, fp16) into Hs, swizzle kp ^ (g<<2) ----
#pragma unroll
    for (int mi = 0; mi < 2; mi++) {
        int ra = wm * 32 + mi * 16 + g;
        int rb = ra + 8;
#pragma unroll
        for (int nj = 0; nj < NJ; nj++) {
            int col = wn * 64 + nj * 8 + 2 * tig;
            float bx = b1[col], by = b1[col + 1];
            float v0 = fmaxf(c[mi][nj][0] + bx, 0.f);
            float v1 = fmaxf(c[mi][nj][1] + by, 0.f);
            float v2 = fmaxf(c[mi][nj][2] + bx, 0.f);
            float v3 = fmaxf(c[mi][nj][3] + by, 0.f);
            int cp = wn * 32 + nj * 4 + tig;
            Hs[ra * 64 + (cp ^ (g << 2))] = f2h2(v0, v1);
            Hs[rb * 64 + (cp ^ (g << 2))] = f2h2(v2, v3);
        }
    }

    // ---- load W2 [128,64] into B2s, swizzle n ^ ((kp&3)<<3) ----
#pragma unroll
    for (int i = 0; i < 4; i++) {
        int idx = tid + i * 256;
        int kp = idx >> 4;
        int n4 = (idx & 15) * 4;
        float4 ev = *(const float4*)(W2 + (size_t)(2 * kp)     * 64 + n4);
        float4 ov = *(const float4*)(W2 + (size_t)(2 * kp + 1) * 64 + n4);
        uint4 t = make_uint4(f2h2(ev.x, ov.x), f2h2(ev.y, ov.y),
                             f2h2(ev.z, ov.z), f2h2(ev.w, ov.w));
        *(uint4*)&B2s[kp * 64 + (n4 ^ ((kp & 3) << 3))] = t;
    }
    __syncthreads();

    // ---- stage 2: [128,128] @ [128,64], 8 k16 steps ----
    float c2[2][4][4];
#pragma unroll
    for (int mi = 0; mi < 2; mi++)
#pragma unroll
        for (int nj = 0; nj < 4; nj++)
#pragma unroll
            for (int q = 0; q < 4; q++) c2[mi][nj][q] = 0.0f;

#pragma unroll
    for (int ks8 = 0; ks8 < 8; ks8++) {
        int kp0 = ks8 * 8;
        uint32_t af[2][4];
#pragma unroll
        for (int mi = 0; mi < 2; mi++) {
            int mb = wm * 32 + mi * 16;
            af[mi][0] = Hs[(mb + g)     * 64 + ((kp0 + tig)     ^ (g << 2))];
            af[mi][1] = Hs[(mb + 8 + g) * 64 + ((kp0 + tig)     ^ (g << 2))];
            af[mi][2] = Hs[(mb + g)     * 64 + ((kp0 + tig + 4) ^ (g << 2))];
            af[mi][3] = Hs[(mb + 8 + g) * 64 + ((kp0 + tig + 4) ^ (g << 2))];
        }
        uint32_t bf[4][2];
#pragma unroll
        for (int nj = 0; nj < 4; nj++) {
            int nb = wn * 32 + nj * 8 + g;
            bf[nj][0] = B2s[(kp0 + tig)     * 64 + (nb ^ (tig << 3))];
            bf[nj][1] = B2s[(kp0 + tig + 4) * 64 + (nb ^ (tig << 3))];
        }
#pragma unroll
        for (int mi = 0; mi < 2; mi++)
#pragma unroll
            for (int nj = 0; nj < 4; nj++)
                MMA_F16(c2[mi][nj], af[mi], bf[nj]);
    }

    // ---- store h_final (fp32, + b2) ----
#pragma unroll
    for (int mi = 0; mi < 2; mi++) {
        int ra = m0 + wm * 32 + mi * 16 + g;
        int rb = ra + 8;
#pragma unroll
        for (int nj = 0; nj < 4; nj++) {
            int col = wn * 32 + nj * 8 + 2 * tig;
            float bx = b2[col], by = b2[col + 1];
            if (ra < M) *(float2*)&outF[(size_t)ra * 64 + col] =
                make_float2(c2[mi][nj][0] + bx, c2[mi][nj][1] + by);
            if (rb < M) *(float2*)&outF[(size_t)rb * 64 + col] =
                make_float2(c2[mi][nj][2] + bx, c2[mi][nj][3] + by);
        }
    }
}

// ------------------------- launcher ------------------------------------------
extern "C" void kernel_launch(void* const* d_in, const int* in_sizes, int n_in,
                              void* d_out, int out_size) {
    const float* features = (const float*)d_in[0];
    const int*   pos_src  = (const int*)d_in[1];
    const int*   pos_dst  = (const int*)d_in[2];
    const int*   neg_src  = (const int*)d_in[3];
    const int*   neg_dst  = (const int*)d_in[4];
    const float* W_pos    = (const float*)d_in[5];
    const float* al_pos   = (const float*)d_in[6];
    const float* ar_pos   = (const float*)d_in[7];
    const float* b_pos    = (const float*)d_in[8];
    const float* W_neg    = (const float*)d_in[9];
    const float* al_neg   = (const float*)d_in[10];
    const float* ar_neg   = (const float*)d_in[11];
    const float* b_neg    = (const float*)d_in[12];
    const float* W1       = (const float*)d_in[13];
    const float* b1       = (const float*)d_in[14];
    const float* W2       = (const float*)d_in[15];
    const float* b2       = (const float*)d_in[16];
    float* out = (float*)d_out;

    int n = in_sizes[0] / HIDDEN;   // 100000
    int e = in_sizes[1];            // 600000

    void* p;
    cudaGetSymbolAddress(&p, g_feat16); __half* featp = (__half*)p;
    cudaGetSymbolAddress(&p, g_el);     float*  elp   = (float*)p;
    cudaGetSymbolAddress(&p, g_er);     float*  erp   = (float*)p;

    float* h_pos   = out;
    float* h_neg   = out + (size_t)n * HIDDEN;
    float* h_final = out + (size_t)2 * n * HIDDEN;

    int gb   = (n + 127) / 128;
    int nseg = 2 * n;
    int nb   = (nseg + 1023) / 1024;

    // Fork a side stream for the CSR build (independent of the feature GEMMs).
    cudaStream_t s1;
    cudaEvent_t ev_fork, ev_join;
    cudaStreamCreateWithFlags(&s1, cudaStreamNonBlocking);
    cudaEventCreateWithFlags(&ev_fork, cudaEventDisableTiming);
    cudaEventCreateWithFlags(&ev_join, cudaEventDisableTiming);

    cudaEventRecord(ev_fork, 0);
    cudaStreamWaitEvent(s1, ev_fork, 0);

    // --- side stream: CSR build (3 kernels; g_cnt/g_total self-reinitializing) ---
    hist_kernel<<<(2 * e + 255) / 256, 256, 0, s1>>>(pos_dst, neg_dst, e);
    scan_fused<<<nb, 256, 0, s1>>>(nseg);
    scatter_kernel<<<(2 * e + 255) / 256, 256, 0, s1>>>(pos_src, pos_dst, neg_src, neg_dst, e);
    cudaEventRecord(ev_join, s1);

    // --- main stream: feature transform GEMMs (fp16 MMA, both signs) ---
    {
        dim3 grid(gb, 2);
        gemm_feat<<<grid, 256>>>(
            features, n, HIDDEN,
            W_pos, W_neg,
            featp, featp + (size_t)NNODES * HIDDEN,
            al_pos, ar_pos, elp, erp,
            al_neg, ar_neg,
            elp + (size_t)NNODES * HEADS, erp + (size_t)NNODES * HEADS);
    }

    // join: aggregation needs both CSR and features
    cudaStreamWaitEvent(0, ev_join, 0);

    // --- fused softmax + aggregation + normalize + bias (h_pos | h_neg) ---
    {
        int nwarps = (2 * n + 1) / 2;            // half-warp per segment
        int gwb = (nwarps + 7) / 8;              // 8 warps per 256-thread block
        aggregate_kernel<<<gwb, 256>>>(out, b_pos, b_neg, n);
    }

    // --- fused MLP: h_final = relu([h_pos|h_neg] @ W1 + b1) @ W2 + b2 ---
    mlp_fused<<<gb, 256>>>(h_pos, h_neg, n, W1, b1, W2, b2, h_final);
}